// round 1
// baseline (speedup 1.0000x reference)
#include <cuda_runtime.h>

#define P_PER_BLOCK 16
#define JETS 13
#define ZROWS 14            // 13 jets + one permanently-zero row
#define HDIM 20
#define NTHREADS (P_PER_BLOCK * JETS)   // 208

// lb/ub reduction state
__device__ unsigned g_min_enc;
__device__ unsigned g_max_enc;

__device__ __forceinline__ unsigned enc_f(float f) {
    unsigned u = __float_as_uint(f);
    return (u & 0x80000000u) ? ~u : (u | 0x80000000u);
}
__device__ __forceinline__ float dec_f(unsigned e) {
    unsigned u = (e & 0x80000000u) ? (e ^ 0x80000000u) : ~e;
    return __uint_as_float(u);
}

__global__ void k_init_minmax() {
    g_min_enc = 0xFFFFFFFFu;
    g_max_enc = 0u;
}

__global__ void k_reduce_minmax(const float* __restrict__ X, int n) {
    unsigned mn = 0xFFFFFFFFu, mx = 0u;
    for (int i = blockIdx.x * blockDim.x + threadIdx.x; i < n;
         i += gridDim.x * blockDim.x) {
        unsigned e = enc_f(X[3 * i]);   // x-coordinate only
        mn = min(mn, e);
        mx = max(mx, e);
    }
    #pragma unroll
    for (int o = 16; o; o >>= 1) {
        mn = min(mn, __shfl_xor_sync(0xffffffffu, mn, o));
        mx = max(mx, __shfl_xor_sync(0xffffffffu, mx, o));
    }
    if ((threadIdx.x & 31) == 0) {
        atomicMin(&g_min_enc, mn);
        atomicMax(&g_max_enc, mx);
    }
}

// Jet order: 0:val 1:x 2:y 3:t 4:xx 5:xy 6:yy 7:xt 8:yt 9:xxx 10:xxy 11:xyy 12:yyy
// Branch-free combine operand tables (row 13 == zero row).
// h_new = s*( z_self - 2h*(zf*zde + ze*zdf + zd*zef) + (4h^2-2s)*zd*ze*zf )
//   order-1 jets: all operands -> zero row  => s*z
//   order-2 (d,e): zd=d, ze=e, zf=0, zde=0, zdf=0, zef=e => s*(z - 2h zd ze)
//   order-3: true indices.
__constant__ int c_jd[JETS]  = {13, 13, 13, 13, 1, 1, 2, 1, 2, 1, 1, 1, 2};
__constant__ int c_je[JETS]  = {13, 13, 13, 13, 1, 2, 2, 3, 3, 1, 1, 2, 2};
__constant__ int c_jf[JETS]  = {13, 13, 13, 13, 13, 13, 13, 13, 13, 1, 2, 2, 2};
__constant__ int c_jde[JETS] = {13, 13, 13, 13, 13, 13, 13, 13, 13, 4, 4, 5, 6};
__constant__ int c_jdf[JETS] = {13, 13, 13, 13, 13, 13, 13, 13, 13, 4, 5, 5, 6};
__constant__ int c_jef[JETS] = {13, 13, 13, 13, 1, 2, 2, 3, 3, 4, 5, 6, 6};

template <int DIN, int DOUT>
__device__ __forceinline__ void layer_step(
    float (&h)[HDIM], const float* __restrict__ Wl, const float* __restrict__ bl,
    float* zp, float* hp, int jet,
    int id, int ie, int iff, int ide, int idf, int ief)
{
    float z[DOUT];
    #pragma unroll
    for (int j = 0; j < DOUT; j++) z[j] = (jet == 0) ? bl[j] : 0.0f;
    #pragma unroll
    for (int i = 0; i < DIN; i++) {
        float hv = h[i];
        #pragma unroll
        for (int j = 0; j < DOUT; j++) z[j] = fmaf(hv, Wl[i * DOUT + j], z[j]);
    }

    __syncthreads();   // previous layer's zbuf/hbuf readers are done
    #pragma unroll
    for (int j = 0; j < DOUT; j++) zp[jet * HDIM + j] = z[j];
    __syncthreads();   // z jets visible

    // cooperative tanh of the value jet (row 0)
    for (int u = jet; u < DOUT; u += JETS) {
        hp[u] = tanhf(zp[u]);
    }
    __syncthreads();   // hbuf visible

    #pragma unroll
    for (int j = 0; j < DOUT; j++) {
        float h0 = hp[j];
        float s  = 1.0f - h0 * h0;
        if (jet == 0) {
            h[j] = h0;
        } else {
            float zd  = zp[id  + j], ze  = zp[ie  + j], zf  = zp[iff + j];
            float zde = zp[ide + j], zdf = zp[idf + j], zef = zp[ief + j];
            float term = zf * zde + ze * zdf + zd * zef;
            float cub  = zd * ze * zf;
            h[j] = s * (z[j] - 2.0f * h0 * term + (4.0f * h0 * h0 - 2.0f * s) * cub);
        }
    }
}

__global__ void __launch_bounds__(NTHREADS)
pinn_kernel(const float* __restrict__ X,
            const float* __restrict__ W1, const float* __restrict__ b1,
            const float* __restrict__ W2, const float* __restrict__ b2,
            const float* __restrict__ W3, const float* __restrict__ b3,
            const float* __restrict__ W4, const float* __restrict__ b4,
            const float* __restrict__ W5, const float* __restrict__ b5,
            const float* __restrict__ W6, const float* __restrict__ b6,
            const float* __restrict__ W7, const float* __restrict__ b7,
            const float* __restrict__ W8, const float* __restrict__ b8,
            const float* __restrict__ lam1p, const float* __restrict__ lam2p,
            float* __restrict__ out, int n)
{
    __shared__ float Wsh[2112];
    __shared__ float bsh[128];
    __shared__ float zbuf[P_PER_BLOCK * ZROWS * HDIM];
    __shared__ float hbuf[P_PER_BLOCK * HDIM];

    const int tid = threadIdx.x;

    // weight/bias layer offsets within shared (16B-aligned)
    const int WOFF[8] = {0, 12, 72, 472, 872, 1272, 1672, 2072};
    const int WSZ[8]  = {9, 60, 400, 400, 400, 400, 400, 40};
    const int BOFF[8] = {0, 4, 24, 44, 64, 84, 104, 124};
    const int BSZ[8]  = {3, 20, 20, 20, 20, 20, 20, 2};
    const float* Wg[8] = {W1, W2, W3, W4, W5, W6, W7, W8};
    const float* Bg[8] = {b1, b2, b3, b4, b5, b6, b7, b8};

    #pragma unroll
    for (int l = 0; l < 8; l++) {
        for (int i = tid; i < WSZ[l]; i += NTHREADS) Wsh[WOFF[l] + i] = Wg[l][i];
        for (int i = tid; i < BSZ[l]; i += NTHREADS) bsh[BOFF[l] + i] = Bg[l][i];
    }
    // zero the permanent zero-row (row 13) for every point in the block
    for (int i = tid; i < P_PER_BLOCK * HDIM; i += NTHREADS) {
        int p = i / HDIM, u = i % HDIM;
        zbuf[p * ZROWS * HDIM + 13 * HDIM + u] = 0.0f;
    }
    __syncthreads();

    const int jet = tid % JETS;
    const int p   = tid / JETS;
    const int gp  = blockIdx.x * P_PER_BLOCK + p;
    const int gpc = (gp < n) ? gp : (n - 1);

    const float lb = dec_f(g_min_enc);
    const float ub = dec_f(g_max_enc);
    const float sc = 2.0f / (ub - lb);

    const float x0 = X[3 * gpc + 0];
    const float x1 = X[3 * gpc + 1];
    const float x2 = X[3 * gpc + 2];

    float h[HDIM];
    #pragma unroll
    for (int i = 0; i < HDIM; i++) h[i] = 0.0f;
    if (jet == 0) {
        h[0] = sc * (x0 - lb) - 1.0f;
        h[1] = sc * (x1 - lb) - 1.0f;
        h[2] = sc * (x2 - lb) - 1.0f;
    } else if (jet == 1) h[0] = sc;
    else if (jet == 2)   h[1] = sc;
    else if (jet == 3)   h[2] = sc;

    float* zp = &zbuf[p * ZROWS * HDIM];
    float* hp = &hbuf[p * HDIM];

    const int id  = c_jd[jet]  * HDIM;
    const int ie  = c_je[jet]  * HDIM;
    const int iff = c_jf[jet]  * HDIM;
    const int ide = c_jde[jet] * HDIM;
    const int idf = c_jdf[jet] * HDIM;
    const int ief = c_jef[jet] * HDIM;

    layer_step<3, 3>  (h, Wsh + WOFF[0], bsh + BOFF[0], zp, hp, jet, id, ie, iff, ide, idf, ief);
    layer_step<3, 20> (h, Wsh + WOFF[1], bsh + BOFF[1], zp, hp, jet, id, ie, iff, ide, idf, ief);
    layer_step<20, 20>(h, Wsh + WOFF[2], bsh + BOFF[2], zp, hp, jet, id, ie, iff, ide, idf, ief);
    layer_step<20, 20>(h, Wsh + WOFF[3], bsh + BOFF[3], zp, hp, jet, id, ie, iff, ide, idf, ief);
    layer_step<20, 20>(h, Wsh + WOFF[4], bsh + BOFF[4], zp, hp, jet, id, ie, iff, ide, idf, ief);
    layer_step<20, 20>(h, Wsh + WOFF[5], bsh + BOFF[5], zp, hp, jet, id, ie, iff, ide, idf, ief);
    layer_step<20, 20>(h, Wsh + WOFF[6], bsh + BOFF[6], zp, hp, jet, id, ie, iff, ide, idf, ief);
    layer_step<20, 2> (h, Wsh + WOFF[7], bsh + BOFF[7], zp, hp, jet, id, ie, iff, ide, idf, ief);

    // publish final jets (units 0 = psi, 1 = p)
    __syncthreads();
    zp[jet * HDIM + 0] = h[0];
    zp[jet * HDIM + 1] = h[1];
    __syncthreads();

    if (tid < P_PER_BLOCK) {
        const float* q = &zbuf[tid * ZROWS * HDIM];
        const int g = blockIdx.x * P_PER_BLOCK + tid;
        if (g < n) {
            // psi jets = unit 0, p jets = unit 1
            float u    =  q[2  * HDIM + 0];   // psi_y
            float v    = -q[1  * HDIM + 0];   // -psi_x
            float pv   =  q[0  * HDIM + 1];
            float p_x  =  q[1  * HDIM + 1];
            float p_y  =  q[2  * HDIM + 1];
            float u_t  =  q[8  * HDIM + 0];   // psi_yt
            float u_x  =  q[5  * HDIM + 0];   // psi_xy
            float u_y  =  q[6  * HDIM + 0];   // psi_yy
            float v_t  = -q[7  * HDIM + 0];   // -psi_xt
            float v_x  = -q[4  * HDIM + 0];   // -psi_xx
            float v_y  = -q[5  * HDIM + 0];   // -psi_xy
            float u_xx =  q[10 * HDIM + 0];   // psi_xxy
            float u_yy =  q[12 * HDIM + 0];   // psi_yyy
            float v_xx = -q[9  * HDIM + 0];   // -psi_xxx
            float v_yy = -q[11 * HDIM + 0];   // -psi_xyy

            float l1 = lam1p[0];
            float l2 = lam2p[0];
            float f_u = u_t + l1 * (u * u_x + v * u_y) + p_x - l2 * (u_xx + u_yy);
            float f_v = v_t + l1 * (u * v_x + v * v_y) + p_y - l2 * (v_xx + v_yy);

            out[0 * n + g] = u;
            out[1 * n + g] = v;
            out[2 * n + g] = pv;
            out[3 * n + g] = f_u;
            out[4 * n + g] = f_v;
        }
    }
}

extern "C" void kernel_launch(void* const* d_in, const int* in_sizes, int n_in,
                              void* d_out, int out_size) {
    const float* X    = (const float*)d_in[0];
    const float* W1   = (const float*)d_in[1];
    const float* b1   = (const float*)d_in[2];
    const float* W2   = (const float*)d_in[3];
    const float* b2   = (const float*)d_in[4];
    const float* W3   = (const float*)d_in[5];
    const float* b3   = (const float*)d_in[6];
    const float* W4   = (const float*)d_in[7];
    const float* b4   = (const float*)d_in[8];
    const float* W5   = (const float*)d_in[9];
    const float* b5   = (const float*)d_in[10];
    const float* W6   = (const float*)d_in[11];
    const float* b6   = (const float*)d_in[12];
    const float* W7   = (const float*)d_in[13];
    const float* b7   = (const float*)d_in[14];
    const float* W8   = (const float*)d_in[15];
    const float* b8   = (const float*)d_in[16];
    const float* lam1 = (const float*)d_in[17];
    const float* lam2 = (const float*)d_in[18];
    float* out = (float*)d_out;

    int n = in_sizes[0] / 3;

    k_init_minmax<<<1, 1>>>();
    k_reduce_minmax<<<128, 256>>>(X, n);

    int blocks = (n + P_PER_BLOCK - 1) / P_PER_BLOCK;
    pinn_kernel<<<blocks, NTHREADS>>>(X, W1, b1, W2, b2, W3, b3, W4, b4,
                                      W5, b5, W6, b6, W7, b7, W8, b8,
                                      lam1, lam2, out, n);
}

// round 2
// speedup vs baseline: 1.1670x; 1.1670x over previous
#include <cuda_runtime.h>

typedef unsigned long long ull;

#define NTHREADS 256
#define GROUP 16            // lanes per point
#define PPB (NTHREADS / GROUP)   // 16 points per block
#define GPART 32            // minmax partial blocks

// ---------------- packed f32x2 helpers (sm_103a) ----------------
__device__ __forceinline__ ull fma2(ull a, ull b, ull c) {
    ull d; asm("fma.rn.f32x2 %0,%1,%2,%3;" : "=l"(d) : "l"(a), "l"(b), "l"(c)); return d;
}
__device__ __forceinline__ ull mul2(ull a, ull b) {
    ull d; asm("mul.rn.f32x2 %0,%1,%2;" : "=l"(d) : "l"(a), "l"(b)); return d;
}
__device__ __forceinline__ ull pack2(float lo, float hi) {
    ull d; asm("mov.b64 %0,{%1,%2};" : "=l"(d) : "f"(lo), "f"(hi)); return d;
}
__device__ __forceinline__ void unpack2(ull v, float& lo, float& hi) {
    asm("mov.b64 {%0,%1},%2;" : "=f"(lo), "=f"(hi) : "l"(v));
}
__device__ __forceinline__ ull shfl64(ull v, int src) {
    float lo, hi; unpack2(v, lo, hi);
    lo = __shfl_sync(0xffffffffu, lo, src, GROUP);
    hi = __shfl_sync(0xffffffffu, hi, src, GROUP);
    return pack2(lo, hi);
}

#define ONE2    0x3F8000003F800000ull
#define NEGONE2 0xBF800000BF800000ull
#define NEGTWO2 0xC0000000C0000000ull
#define SIX2    0x40C0000040C00000ull

// ---------------- lb/ub reduction ----------------
__device__ unsigned g_pmin[GPART];
__device__ unsigned g_pmax[GPART];

__device__ __forceinline__ unsigned enc_f(float f) {
    unsigned u = __float_as_uint(f);
    return (u & 0x80000000u) ? ~u : (u | 0x80000000u);
}
__device__ __forceinline__ float dec_f(unsigned e) {
    unsigned u = (e & 0x80000000u) ? (e ^ 0x80000000u) : ~e;
    return __uint_as_float(u);
}

__global__ void k_partial_minmax(const float* __restrict__ X, int n) {
    __shared__ unsigned smn[8], smx[8];
    unsigned mn = 0xFFFFFFFFu, mx = 0u;
    for (int i = blockIdx.x * blockDim.x + threadIdx.x; i < n;
         i += gridDim.x * blockDim.x) {
        unsigned e = enc_f(X[3 * i]);
        mn = min(mn, e); mx = max(mx, e);
    }
    #pragma unroll
    for (int o = 16; o; o >>= 1) {
        mn = min(mn, __shfl_xor_sync(0xffffffffu, mn, o));
        mx = max(mx, __shfl_xor_sync(0xffffffffu, mx, o));
    }
    int w = threadIdx.x >> 5;
    if ((threadIdx.x & 31) == 0) { smn[w] = mn; smx[w] = mx; }
    __syncthreads();
    if (threadIdx.x == 0) {
        #pragma unroll
        for (int i = 1; i < 8; i++) { mn = min(mn, smn[i]); mx = max(mx, smx[i]); }
        g_pmin[blockIdx.x] = mn;
        g_pmax[blockIdx.x] = mx;
    }
}

// Jet order: 0:val 1:x 2:y 3:t 4:xx 5:xy 6:yy 7:xt 8:yt 9:xxx 10:xxy 11:xyy 12:yyy
// h^{def} = s*( z^{def} - 2h(z^f z^{de} + z^e z^{df} + z^d z^{ef}) + (4h^2-2s) z^d z^e z^f )
// order-1: all masked -> s*z ; order-2 (d,e): md=1, ef->e  -> s*(z - 2h zd ze)
__constant__ int   c_sd[13]  = {0,0,0,0, 1,1,2,1,2, 1,1,1,2};
__constant__ int   c_se[13]  = {0,0,0,0, 1,2,2,3,3, 1,1,2,2};
__constant__ int   c_sf[13]  = {0,0,0,0, 0,0,0,0,0, 1,2,2,2};
__constant__ int   c_sde[13] = {0,0,0,0, 0,0,0,0,0, 4,4,5,6};
__constant__ int   c_sdf[13] = {0,0,0,0, 0,0,0,0,0, 4,5,5,6};
__constant__ int   c_sef[13] = {0,0,0,0, 1,2,2,3,3, 4,5,6,6};
__constant__ float c_md[13]  = {0,0,0,0, 1,1,1,1,1, 1,1,1,1};
__constant__ float c_mf[13]  = {0,0,0,0, 0,0,0,0,0, 1,1,1,1};
__constant__ float c_mde[13] = {0,0,0,0, 0,0,0,0,0, 1,1,1,1};
__constant__ float c_mdf[13] = {0,0,0,0, 0,0,0,0,0, 1,1,1,1};

// One layer: matmul (packed f32x2), distributed tanh, shuffle-based jet combine.
template <int DIN, int DOUT>
__device__ __forceinline__ void layer_step(
    float (&h)[20], const float* __restrict__ Wl, const float* __restrict__ bl,
    int jet, bool isjet0,
    int sd, int se, int sf, int sde, int sdf, int sef,
    ull mdp, ull mfp, ull mdep, ull mdfp)
{
    constexpr int P2 = DOUT / 2;
    constexpr int P4 = DOUT / 4;
    static_assert(DOUT % 4 == 0, "DOUT must be padded to multiple of 4");

    ull z2[P2];
    const float4* Wv = reinterpret_cast<const float4*>(Wl);
    const float4* Bv = reinterpret_cast<const float4*>(bl);

    if (isjet0) {
        #pragma unroll
        for (int p = 0; p < P4; p++) {
            float4 b = Bv[p];
            z2[2 * p]     = pack2(b.x, b.y);
            z2[2 * p + 1] = pack2(b.z, b.w);
        }
    } else {
        #pragma unroll
        for (int q = 0; q < P2; q++) z2[q] = 0ull;
    }

    #pragma unroll
    for (int i = 0; i < DIN; i++) {
        ull hh = pack2(h[i], h[i]);
        #pragma unroll
        for (int p = 0; p < P4; p++) {
            float4 w = Wv[i * P4 + p];
            z2[2 * p]     = fma2(hh, pack2(w.x, w.y), z2[2 * p]);
            z2[2 * p + 1] = fma2(hh, pack2(w.z, w.w), z2[2 * p + 1]);
        }
    }

    // distribute tanh: lane q owns units {2q, 2q+1}
    ull myz0 = 0ull;
    #pragma unroll
    for (int q = 0; q < P2; q++) {
        ull v = shfl64(z2[q], 0);
        if (jet == q) myz0 = v;
    }
    float tl, th; unpack2(myz0, tl, th);
    ull t2 = pack2(tanhf(tl), tanhf(th));

    // combine
    #pragma unroll
    for (int q = 0; q < P2; q++) {
        ull h0p = shfl64(t2, q);
        ull zd  = shfl64(z2[q], sd);
        ull ze  = shfl64(z2[q], se);
        ull zf  = shfl64(z2[q], sf);
        ull zde = shfl64(z2[q], sde);
        ull zdf = shfl64(z2[q], sdf);
        ull zef = shfl64(z2[q], sef);
        zd  = mul2(zd, mdp);
        zf  = mul2(zf, mfp);
        zde = mul2(zde, mdep);
        zdf = mul2(zdf, mdfp);
        ull T   = mul2(zf, zde);
        T       = fma2(ze, zdf, T);
        T       = fma2(zd, zef, T);
        ull cub = mul2(mul2(zd, ze), zf);
        ull hq  = mul2(h0p, h0p);
        ull s   = fma2(hq, NEGONE2, ONE2);     // 1 - h0^2
        ull C   = fma2(hq, SIX2, NEGTWO2);     // 4h0^2 - 2s = 6h0^2 - 2
        ull n2h = mul2(h0p, NEGTWO2);
        ull r   = fma2(n2h, T, z2[q]);
        r       = fma2(C, cub, r);
        ull hn  = mul2(s, r);
        if (isjet0) hn = h0p;
        unpack2(hn, h[2 * q], h[2 * q + 1]);
    }
}

__global__ void __launch_bounds__(NTHREADS)
pinn_kernel(const float* __restrict__ X,
            const float* __restrict__ W1, const float* __restrict__ b1,
            const float* __restrict__ W2, const float* __restrict__ b2,
            const float* __restrict__ W3, const float* __restrict__ b3,
            const float* __restrict__ W4, const float* __restrict__ b4,
            const float* __restrict__ W5, const float* __restrict__ b5,
            const float* __restrict__ W6, const float* __restrict__ b6,
            const float* __restrict__ W7, const float* __restrict__ b7,
            const float* __restrict__ W8, const float* __restrict__ b8,
            const float* __restrict__ lam1p, const float* __restrict__ lam2p,
            float* __restrict__ out, int n)
{
    __shared__ float Wsh[2152];
    __shared__ float bsh[128];

    const int tid = threadIdx.x;

    // padded layer layout (DOUT padded to multiple of 4)
    const int WOFF[8] = {0, 12, 72, 472, 872, 1272, 1672, 2072};
    const int LDIN[8] = {3, 3, 20, 20, 20, 20, 20, 20};
    const int DSRC[8] = {3, 20, 20, 20, 20, 20, 20, 2};
    const int DPAD[8] = {4, 20, 20, 20, 20, 20, 20, 4};
    const int BOFF[8] = {0, 4, 24, 44, 64, 84, 104, 124};
    const float* Wg[8] = {W1, W2, W3, W4, W5, W6, W7, W8};
    const float* Bg[8] = {b1, b2, b3, b4, b5, b6, b7, b8};

    #pragma unroll
    for (int l = 0; l < 8; l++) {
        int tot = LDIN[l] * DPAD[l];
        for (int i = tid; i < tot; i += NTHREADS) {
            int r = i / DPAD[l], c = i % DPAD[l];
            Wsh[WOFF[l] + i] = (c < DSRC[l]) ? Wg[l][r * DSRC[l] + c] : 0.0f;
        }
        for (int i = tid; i < DPAD[l]; i += NTHREADS)
            bsh[BOFF[l] + i] = (i < DSRC[l]) ? Bg[l][i] : 0.0f;
    }
    __syncthreads();   // the only block barrier

    // final lb/ub reduction (uniform across threads, L1-broadcast)
    unsigned mn = 0xFFFFFFFFu, mx = 0u;
    #pragma unroll
    for (int i = 0; i < GPART; i++) {
        mn = min(mn, g_pmin[i]);
        mx = max(mx, g_pmax[i]);
    }
    const float lb = dec_f(mn);
    const float ub = dec_f(mx);
    const float sc = 2.0f / (ub - lb);

    const int lane = tid & (GROUP - 1);
    const int jet  = lane;                 // 13..15 inactive
    const int jc   = (jet < 13) ? jet : 12;
    const bool isjet0 = (jet == 0);

    const int p  = tid >> 4;               // point within block
    const int gp = blockIdx.x * PPB + p;
    const int gpc = (gp < n) ? gp : (n - 1);

    const float x0 = X[3 * gpc + 0];
    const float x1 = X[3 * gpc + 1];
    const float x2 = X[3 * gpc + 2];

    float h[20];
    h[0] = 0.0f; h[1] = 0.0f; h[2] = 0.0f;
    if (jet == 0) {
        h[0] = sc * (x0 - lb) - 1.0f;
        h[1] = sc * (x1 - lb) - 1.0f;
        h[2] = sc * (x2 - lb) - 1.0f;
    } else if (jet == 1) h[0] = sc;
    else if (jet == 2)   h[1] = sc;
    else if (jet == 3)   h[2] = sc;

    const int sd  = c_sd[jc],  se  = c_se[jc],  sf  = c_sf[jc];
    const int sde = c_sde[jc], sdf = c_sdf[jc], sef = c_sef[jc];
    const ull mdp  = pack2(c_md[jc],  c_md[jc]);
    const ull mfp  = pack2(c_mf[jc],  c_mf[jc]);
    const ull mdep = pack2(c_mde[jc], c_mde[jc]);
    const ull mdfp = pack2(c_mdf[jc], c_mdf[jc]);

    layer_step<3, 4>  (h, Wsh + WOFF[0], bsh + BOFF[0], jet, isjet0, sd, se, sf, sde, sdf, sef, mdp, mfp, mdep, mdfp);
    layer_step<3, 20> (h, Wsh + WOFF[1], bsh + BOFF[1], jet, isjet0, sd, se, sf, sde, sdf, sef, mdp, mfp, mdep, mdfp);
    layer_step<20, 20>(h, Wsh + WOFF[2], bsh + BOFF[2], jet, isjet0, sd, se, sf, sde, sdf, sef, mdp, mfp, mdep, mdfp);
    layer_step<20, 20>(h, Wsh + WOFF[3], bsh + BOFF[3], jet, isjet0, sd, se, sf, sde, sdf, sef, mdp, mfp, mdep, mdfp);
    layer_step<20, 20>(h, Wsh + WOFF[4], bsh + BOFF[4], jet, isjet0, sd, se, sf, sde, sdf, sef, mdp, mfp, mdep, mdfp);
    layer_step<20, 20>(h, Wsh + WOFF[5], bsh + BOFF[5], jet, isjet0, sd, se, sf, sde, sdf, sef, mdp, mfp, mdep, mdfp);
    layer_step<20, 20>(h, Wsh + WOFF[6], bsh + BOFF[6], jet, isjet0, sd, se, sf, sde, sdf, sef, mdp, mfp, mdep, mdfp);
    layer_step<20, 4> (h, Wsh + WOFF[7], bsh + BOFF[7], jet, isjet0, sd, se, sf, sde, sdf, sef, mdp, mfp, mdep, mdfp);

    // epilogue: gather jets to lane 0 of each 16-lane group
    const float psi = h[0];
    const float pp  = h[1];
    const unsigned FULL = 0xffffffffu;

    float uu   =  __shfl_sync(FULL, psi, 2,  GROUP);   // psi_y
    float vv   = -__shfl_sync(FULL, psi, 1,  GROUP);   // -psi_x
    float pvv  =  __shfl_sync(FULL, pp,  0,  GROUP);
    float p_x  =  __shfl_sync(FULL, pp,  1,  GROUP);
    float p_y  =  __shfl_sync(FULL, pp,  2,  GROUP);
    float u_t  =  __shfl_sync(FULL, psi, 8,  GROUP);   // psi_yt
    float u_x  =  __shfl_sync(FULL, psi, 5,  GROUP);   // psi_xy
    float u_y  =  __shfl_sync(FULL, psi, 6,  GROUP);   // psi_yy
    float v_t  = -__shfl_sync(FULL, psi, 7,  GROUP);   // -psi_xt
    float v_x  = -__shfl_sync(FULL, psi, 4,  GROUP);   // -psi_xx
    float v_y  = -u_x;                                 // -psi_xy
    float u_xx =  __shfl_sync(FULL, psi, 10, GROUP);   // psi_xxy
    float u_yy =  __shfl_sync(FULL, psi, 12, GROUP);   // psi_yyy
    float v_xx = -__shfl_sync(FULL, psi, 9,  GROUP);   // -psi_xxx
    float v_yy = -__shfl_sync(FULL, psi, 11, GROUP);   // -psi_xyy

    if (lane == 0 && gp < n) {
        float l1 = lam1p[0];
        float l2 = lam2p[0];
        float f_u = u_t + l1 * (uu * u_x + vv * u_y) + p_x - l2 * (u_xx + u_yy);
        float f_v = v_t + l1 * (uu * v_x + vv * v_y) + p_y - l2 * (v_xx + v_yy);
        out[0 * n + gp] = uu;
        out[1 * n + gp] = vv;
        out[2 * n + gp] = pvv;
        out[3 * n + gp] = f_u;
        out[4 * n + gp] = f_v;
    }
}

extern "C" void kernel_launch(void* const* d_in, const int* in_sizes, int n_in,
                              void* d_out, int out_size) {
    const float* X    = (const float*)d_in[0];
    const float* W1   = (const float*)d_in[1];
    const float* b1   = (const float*)d_in[2];
    const float* W2   = (const float*)d_in[3];
    const float* b2   = (const float*)d_in[4];
    const float* W3   = (const float*)d_in[5];
    const float* b3   = (const float*)d_in[6];
    const float* W4   = (const float*)d_in[7];
    const float* b4   = (const float*)d_in[8];
    const float* W5   = (const float*)d_in[9];
    const float* b5   = (const float*)d_in[10];
    const float* W6   = (const float*)d_in[11];
    const float* b6   = (const float*)d_in[12];
    const float* W7   = (const float*)d_in[13];
    const float* b7   = (const float*)d_in[14];
    const float* W8   = (const float*)d_in[15];
    const float* b8   = (const float*)d_in[16];
    const float* lam1 = (const float*)d_in[17];
    const float* lam2 = (const float*)d_in[18];
    float* out = (float*)d_out;

    int n = in_sizes[0] / 3;

    k_partial_minmax<<<GPART, 256>>>(X, n);

    int blocks = (n + PPB - 1) / PPB;
    pinn_kernel<<<blocks, NTHREADS>>>(X, W1, b1, W2, b2, W3, b3, W4, b4,
                                      W5, b5, W6, b6, W7, b7, W8, b8,
                                      lam1, lam2, out, n);
}